// round 9
// baseline (speedup 1.0000x reference)
#include <cuda_runtime.h>
#include <math.h>

#define B_  2
#define N_  8
#define K_  8
#define C_  256
#define HW_ 9216
#define BN_ (B_*N_)

// ---------------- scratch (__device__ globals: no allocation allowed) -------
__device__ float d_wsum[BN_*C_];       // sum(value*mask) over HW
__device__ float d_vsum[BN_*C_];       // sum(value) over HW
__device__ float d_msum[BN_];          // sum(mask) over HW
__device__ float d_pnew[BN_*K_*C_];    // proto_new
__device__ float d_bnn [BN_*K_*C_];    // l2norm(proto_new)
__device__ float d_vldn[BN_*K_];       // valid_new as float
__device__ int   d_anyv[BN_];          // any(valid_new)
__device__ float d_attn[(size_t)BN_*HW_*K_];  // per-pixel softmax weights (4.7MB)

__device__ __forceinline__ float warpSum(float v) {
    #pragma unroll
    for (int o = 16; o; o >>= 1) v += __shfl_xor_sync(0xffffffffu, v, o);
    return v;
}
__device__ __forceinline__ float warpMax(float v) {
    #pragma unroll
    for (int o = 16; o; o >>= 1) v = fmaxf(v, __shfl_xor_sync(0xffffffffu, v, o));
    return v;
}

// ---------------- kernel 1: masked pooling sums over HW (+ msum) -----------
// grid (C, N, B), 256 threads. Reads full value once. Block x==0 also writes msum.
__global__ void __launch_bounds__(256) k_candsum(const float* __restrict__ value,
                                                 const float* __restrict__ mask) {
    int c  = blockIdx.x;
    int bn = blockIdx.z * N_ + blockIdx.y;
    int t  = threadIdx.x;
    const float4* v4 = (const float4*)(value + ((size_t)bn * C_ + c) * HW_);
    const float4* m4 = (const float4*)(mask + (size_t)bn * HW_);
    float ws = 0.f, vs = 0.f, ms = 0.f;
    #pragma unroll
    for (int i = 0; i < 9; i++) {                          // 9216/4/256 = 9
        float4 v = v4[i * 256 + t];
        float4 m = m4[i * 256 + t];
        ws += v.x * m.x + v.y * m.y + v.z * m.z + v.w * m.w;
        vs += v.x + v.y + v.z + v.w;
        ms += m.x + m.y + m.z + m.w;
    }
    ws = warpSum(ws); vs = warpSum(vs);
    __shared__ float sw[8], sv[8], sm[8];
    if ((t & 31) == 0) { sw[t >> 5] = ws; sv[t >> 5] = vs; }
    if (c == 0) {
        ms = warpSum(ms);
        if ((t & 31) == 0) sm[t >> 5] = ms;
    }
    __syncthreads();
    if (t == 0) {
        float a = 0.f, b = 0.f;
        #pragma unroll
        for (int i = 0; i < 8; i++) { a += sw[i]; b += sv[i]; }
        d_wsum[bn * C_ + c] = a;
        d_vsum[bn * C_ + c] = b;
        if (c == 0) {
            float r = 0.f;
            #pragma unroll
            for (int i = 0; i < 8; i++) r += sm[i];
            d_msum[bn] = r;
        }
    }
}

// ---------------- kernel 2: policy + bank update (fused small work) ---------
// grid 16, 256 threads. Warp w owns slot w for sims and the final update.
__global__ void __launch_bounds__(256) k_policy(const float* __restrict__ proto,
                                                const float* __restrict__ age,
                                                const float* __restrict__ usage,
                                                const float* __restrict__ conf,
                                                const void* __restrict__ valid) {
    int bn = blockIdx.x, t = threadIdx.x;
    int w = t >> 5, l = t & 31;
    __shared__ float s_cand[C_], s_sim[K_], s_red[8], s_redU[8];
    __shared__ float s_vldf[K_], s_am, s_um;
    __shared__ int s_mode;          // valid dtype sniff
    __shared__ int s_upd, s_act;

    // ---- valid dtype sniff (thread 0) + global age/usage maxes -------------
    if (t == 0) {
        const unsigned int* wd = (const unsigned int*)valid;
        int isInt = 1, isFlt = 1;
        for (int i = 0; i < 32; i++) {
            unsigned int x = wd[i];
            isInt &= (x <= 1u);
            isFlt &= (x == 0u || x == 0x3f800000u);
        }
        s_mode = isInt ? 1 : (isFlt ? 2 : 0);
    }
    {
        float a = (t < 128) ? age[t]   : -1e30f;
        float u = (t < 128) ? usage[t] : -1e30f;
        a = warpMax(a); u = warpMax(u);
        if (l == 0) { s_red[w] = a; s_redU[w] = u; }
    }
    __syncthreads();
    if (t == 0) {
        float A = -1e30f, U = -1e30f;
        #pragma unroll
        for (int i = 0; i < 8; i++) { A = fmaxf(A, s_red[i]); U = fmaxf(U, s_redU[i]); }
        s_am = fmaxf(A, 1.0f); s_um = fmaxf(U, 1.0f);
    }
    if (t < K_) {
        int idx = bn * K_ + t, v;
        if (s_mode == 1)      v = ((const int*)valid)[idx] != 0;          // needs s_mode
        else if (s_mode == 2) v = ((const float*)valid)[idx] != 0.0f;
        else                  v = ((const unsigned char*)valid)[idx] != 0;
        s_vldf[t] = v ? 1.0f : 0.0f;
    }
    __syncthreads();   // NOTE: s_mode written by t0 before this barrier? t<8 read it above!

    // re-decode after barrier to be safe against the race above
    if (t < K_) {
        int idx = bn * K_ + t, v;
        if (s_mode == 1)      v = ((const int*)valid)[idx] != 0;
        else if (s_mode == 2) v = ((const float*)valid)[idx] != 0.0f;
        else                  v = ((const unsigned char*)valid)[idx] != 0;
        s_vldf[t] = v ? 1.0f : 0.0f;
    }
    __syncthreads();

    // ---- candidate prototype (channel t), l2-normalized --------------------
    float msum = d_msum[bn];
    float cc = (msum <= 1e-5f)
             ? d_vsum[bn * C_ + t] * (1.0f / (float)HW_)
             : d_wsum[bn * C_ + t] / fmaxf(msum, 1e-6f);
    float ss = warpSum(cc * cc);
    if (l == 0) s_red[w] = ss;
    __syncthreads();
    float tot = 0.f;
    #pragma unroll
    for (int i = 0; i < 8; i++) tot += s_red[i];
    float cn = cc / fmaxf(sqrtf(tot), 1e-12f);
    s_cand[t] = cn;
    __syncthreads();

    // ---- sim[k]: warp w handles slot w -------------------------------------
    const float* pbase = proto + (size_t)bn * K_ * C_;
    {
        float ps = 0.f, pd = 0.f;
        #pragma unroll
        for (int i = 0; i < 8; i++) {
            float p = pbase[w * C_ + i * 32 + l];
            ps += p * p;
            pd += p * s_cand[i * 32 + l];
        }
        ps = warpSum(ps); pd = warpSum(pd);
        if (l == 0) {
            float sim = pd / fmaxf(sqrtf(ps), 1e-12f);
            s_sim[w] = (s_vldf[w] > 0.5f) ? sim : -1.0f;
        }
    }
    __syncthreads();

    // ---- decision (thread 0) -----------------------------------------------
    if (t == 0) {
        bool v[K_]; bool anyv = false, anyi = false;
        #pragma unroll
        for (int k = 0; k < K_; k++) {
            v[k] = (s_vldf[k] > 0.5f);
            anyv |= v[k]; anyi |= !v[k];
        }
        float best = -1e30f; int tgt = 0;
        #pragma unroll
        for (int k = 0; k < K_; k++) if (s_sim[k] > best) { best = s_sim[k]; tgt = k; }
        int target = anyv ? tgt : 0;
        float msim = anyv ? s_sim[target] : -1.0f;
        // A_KEEP=0, A_REFINE=1, A_SPAWN=3
        int action = (!anyv) ? 3 : ((msim >= 0.8f) ? 1 : ((msim >= 0.3f) ? 0 : 3));
        float am = s_am, um = s_um;
        float bs = -1e30f; int vic = 0;
        #pragma unroll
        for (int k = 0; k < K_; k++) {
            float sc = age[bn * K_ + k] / am
                     + (1.0f - usage[bn * K_ + k] / um)
                     + (1.0f - conf[bn * K_ + k]);
            if (sc > bs) { bs = sc; vic = k; }
        }
        int fe = 0;
        for (int k = 0; k < K_; k++) { if (!v[k]) { fe = k; break; } }
        int spawn = anyi ? fe : vic;
        s_upd = (action == 1) ? target : spawn;
        s_act = (action == 1) ? 1 : ((action == 3) ? 2 : 0);  // 1=refine, 2=spawn
        d_anyv[bn] = (anyv || action == 3) ? 1 : 0;
    }
    __syncthreads();
    int upd = s_upd, mode = s_act;

    // ---- per-warp slot update: warp w owns slot w (no barriers) ------------
    {
        float pr[8], pn[8]; float q = 0.f;
        #pragma unroll
        for (int i = 0; i < 8; i++) {
            float p = pbase[w * C_ + i * 32 + l];
            float x = p;
            if (w == upd) {
                if (mode == 1)      x = 0.7f * p + 0.3f * s_cand[i * 32 + l];
                else if (mode == 2) x = s_cand[i * 32 + l];
            }
            pr[i] = p; pn[i] = x; q += x * x;
        }
        q = warpSum(q);
        float inv = 1.0f / fmaxf(sqrtf(q), 1e-12f);
        size_t o = (size_t)bn * K_ * C_ + (size_t)w * C_;
        bool storeNorm = (w == upd && mode == 1);   // refine slot stores normalized
        #pragma unroll
        for (int i = 0; i < 8; i++) {
            float pw = storeNorm ? pn[i] * inv : pn[i];
            d_pnew[o + i * 32 + l] = pw;
            d_bnn [o + i * 32 + l] = pn[i] * inv;
        }
        if (l == 0) {
            bool vk = (s_vldf[w] > 0.5f);
            d_vldn[bn * K_ + w] = (vk || (mode == 2 && w == upd)) ? 1.0f : 0.0f;
        }
    }
}

// ---------------- kernel 3: attention weights (pure value stream) -----------
// grid (9, N, B) = 144 blocks, 512 threads, 2 px/thread. Writes a[8] per pixel.
__global__ void __launch_bounds__(512) k_attn(const float* __restrict__ value,
                                              float* __restrict__ attnOut) {
    int tile = blockIdx.x, n = blockIdx.y, b = blockIdx.z;
    int bn = b * N_ + n;
    int t = threadIdx.x;
    __shared__ float s_bnnT[C_][K_];   // l2norm(proto_new) transposed [c][k]
    __shared__ float s_vld[K_];
    __shared__ int s_any;
    const size_t off = (size_t)bn * K_ * C_;
    #pragma unroll
    for (int i = 0; i < 4; i++) {
        int j = i * 512 + t;           // j = k*C + c
        s_bnnT[j & 255][j >> 8] = d_bnn[off + j];
    }
    if (t < K_) s_vld[t] = d_vldn[bn * K_ + t];
    if (t == 0) s_any = d_anyv[bn];
    __syncthreads();

    int pix = tile * 1024 + t * 2;
    const float* vb = value + (size_t)bn * C_ * HW_ + pix;

    float ns0 = 0.f, ns1 = 0.f;
    float r0[K_], r1[K_];
    #pragma unroll
    for (int k = 0; k < K_; k++) { r0[k] = 0.f; r1[k] = 0.f; }

    for (int cb = 0; cb < C_; cb += 8) {
        float2 v[8];
        #pragma unroll
        for (int i = 0; i < 8; i++)
            v[i] = *(const float2*)(vb + (size_t)(cb + i) * HW_);
        #pragma unroll
        for (int i = 0; i < 8; i++) {
            ns0 += v[i].x * v[i].x; ns1 += v[i].y * v[i].y;
            float4 p0 = *(const float4*)&s_bnnT[cb + i][0];
            float4 p1 = *(const float4*)&s_bnnT[cb + i][4];
            r0[0] += p0.x * v[i].x; r1[0] += p0.x * v[i].y;
            r0[1] += p0.y * v[i].x; r1[1] += p0.y * v[i].y;
            r0[2] += p0.z * v[i].x; r1[2] += p0.z * v[i].y;
            r0[3] += p0.w * v[i].x; r1[3] += p0.w * v[i].y;
            r0[4] += p1.x * v[i].x; r1[4] += p1.x * v[i].y;
            r0[5] += p1.y * v[i].x; r1[5] += p1.y * v[i].y;
            r0[6] += p1.z * v[i].x; r1[6] += p1.z * v[i].y;
            r0[7] += p1.w * v[i].x; r1[7] += p1.w * v[i].y;
        }
    }
    float i0 = 1.0f / fmaxf(sqrtf(ns0), 1e-12f);
    float i1 = 1.0f / fmaxf(sqrtf(ns1), 1e-12f);

    float a0[K_], a1[K_];
    if (!s_any) {
        #pragma unroll
        for (int k = 0; k < K_; k++) { a0[k] = 0.f; a1[k] = 0.f; }
    } else {
        float m0 = -1e30f, m1 = -1e30f;
        #pragma unroll
        for (int k = 0; k < K_; k++) {
            if (s_vld[k] > 0.5f) {
                m0 = fmaxf(m0, r0[k] * i0);
                m1 = fmaxf(m1, r1[k] * i1);
            }
        }
        float t0 = 0.f, t1 = 0.f;
        #pragma unroll
        for (int k = 0; k < K_; k++) {
            float e0 = (s_vld[k] > 0.5f) ? __expf(r0[k] * i0 - m0) : 0.f;
            float e1 = (s_vld[k] > 0.5f) ? __expf(r1[k] * i1 - m1) : 0.f;
            a0[k] = e0; a1[k] = e1;
            t0 += e0; t1 += e1;
        }
        float z0 = 1.0f / t0, z1 = 1.0f / t1;
        #pragma unroll
        for (int k = 0; k < K_; k++) { a0[k] *= z0; a1[k] *= z1; }
    }

    float4* ao = (float4*)(attnOut + ((size_t)bn * HW_ + pix) * K_);
    ao[0] = make_float4(a0[0], a0[1], a0[2], a0[3]);
    ao[1] = make_float4(a0[4], a0[5], a0[6], a0[7]);
    ao[2] = make_float4(a1[0], a1[1], a1[2], a1[3]);
    ao[3] = make_float4(a1[4], a1[5], a1[6], a1[7]);
}

// ---------------- kernel 4: blend (pure stream) -----------------------------
// grid (18, N, B) = 288 blocks, 256 threads, 2 px/thread.
__global__ void __launch_bounds__(256) k_blend(const float* __restrict__ value,
                                               const float* __restrict__ frame,
                                               const float* __restrict__ attnIn,
                                               const float* __restrict__ pgate,
                                               const float* __restrict__ fgate,
                                               float* __restrict__ out) {
    int tile = blockIdx.x, n = blockIdx.y, b = blockIdx.z;
    int bn = b * N_ + n;
    int t = threadIdx.x;
    __shared__ float s_pnT[C_][K_];    // proto_new transposed [c][k]
    const size_t off = (size_t)bn * K_ * C_;
    #pragma unroll
    for (int i = 0; i < 8; i++) {
        int j = i * 256 + t;
        s_pnT[j & 255][j >> 8] = d_pnew[off + j];
    }
    __syncthreads();

    int pix = tile * 512 + t * 2;
    const float4* ai = (const float4*)(attnIn + ((size_t)bn * HW_ + pix) * K_);
    float4 A0 = ai[0], A1 = ai[1], A2 = ai[2], A3 = ai[3];
    float a0[K_] = {A0.x, A0.y, A0.z, A0.w, A1.x, A1.y, A1.z, A1.w};
    float a1[K_] = {A2.x, A2.y, A2.z, A2.w, A3.x, A3.y, A3.z, A3.w};

    float pg = *pgate, fg = *fgate;
    const float* vb = value + (size_t)bn * C_ * HW_ + pix;
    const float* fb = frame + (size_t)b * C_ * HW_ + pix;
    float* ob = out + (size_t)bn * C_ * HW_ + pix;

    for (int cb = 0; cb < C_; cb += 8) {
        float2 v[8], f[8];
        #pragma unroll
        for (int i = 0; i < 8; i++) {
            v[i] = *(const float2*)(vb + (size_t)(cb + i) * HW_);
            f[i] = *(const float2*)(fb + (size_t)(cb + i) * HW_);
        }
        #pragma unroll
        for (int i = 0; i < 8; i++) {
            float4 p0 = *(const float4*)&s_pnT[cb + i][0];
            float4 p1 = *(const float4*)&s_pnT[cb + i][4];
            float pm0 = a0[0] * p0.x + a0[1] * p0.y + a0[2] * p0.z + a0[3] * p0.w
                      + a0[4] * p1.x + a0[5] * p1.y + a0[6] * p1.z + a0[7] * p1.w;
            float pm1 = a1[0] * p0.x + a1[1] * p0.y + a1[2] * p0.z + a1[3] * p0.w
                      + a1[4] * p1.x + a1[5] * p1.y + a1[6] * p1.z + a1[7] * p1.w;
            float2 o;
            o.x = v[i].x + pg * pm0 + fg * f[i].x;
            o.y = v[i].y + pg * pm1 + fg * f[i].y;
            *(float2*)(ob + (size_t)(cb + i) * HW_) = o;
        }
    }
}

// ---------------- launch ----------------------------------------------------
extern "C" void kernel_launch(void* const* d_in, const int* in_sizes, int n_in,
                              void* d_out, int out_size) {
    const float* value = (const float*)d_in[0];
    const float* frame = (const float*)d_in[1];
    const float* mask  = (const float*)d_in[2];
    const float* proto = (const float*)d_in[3];
    const float* age   = (const float*)d_in[4];
    const float* usage = (const float*)d_in[5];
    const float* conf  = (const float*)d_in[6];
    // d_in[7..10] = W1, b1, W2, b2: dead code (logits unused by the output)
    const float* pgate = (const float*)d_in[11];
    const float* fgate = (const float*)d_in[12];
    const void*  valid = (const void*)d_in[13];
    float* out = (float*)d_out;

    dim3 gc(C_, N_, B_);
    k_candsum<<<gc, 256>>>(value, mask);
    k_policy<<<BN_, 256>>>(proto, age, usage, conf, valid);
    dim3 ga(HW_ / 1024, N_, B_);
    k_attn<<<ga, 512>>>(value, d_attn);
    dim3 gb(HW_ / 512, N_, B_);
    k_blend<<<gb, 256>>>(value, frame, d_attn, pgate, fgate, out);
}

// round 10
// speedup vs baseline: 1.8766x; 1.8766x over previous
#include <cuda_runtime.h>
#include <math.h>

#define B_  2
#define N_  8
#define K_  8
#define C_  256
#define HW_ 9216
#define BN_ (B_*N_)
#define PX_ 64                      // pixels per readout tile

// ---------------- scratch (__device__ globals: no allocation allowed) -------
__device__ float d_wsum[BN_*C_];       // sum(value*mask) over HW
__device__ float d_vsum[BN_*C_];       // sum(value) over HW
__device__ float d_msum[BN_];          // sum(mask) over HW
__device__ float d_pnew[BN_*K_*C_];    // proto_new
__device__ float d_bnn [BN_*K_*C_];    // l2norm(proto_new)
__device__ float d_vldn[BN_*K_];       // valid_new as float
__device__ int   d_anyv[BN_];          // any(valid_new)

__device__ __forceinline__ float warpSum(float v) {
    #pragma unroll
    for (int o = 16; o; o >>= 1) v += __shfl_xor_sync(0xffffffffu, v, o);
    return v;
}
__device__ __forceinline__ float warpMax(float v) {
    #pragma unroll
    for (int o = 16; o; o >>= 1) v = fmaxf(v, __shfl_xor_sync(0xffffffffu, v, o));
    return v;
}

// ---------------- kernel 1: masked pooling sums over HW (+ msum) -----------
// grid (C, N, B), 256 threads. Reads full value once (~5.3 TB/s measured).
__global__ void __launch_bounds__(256) k_candsum(const float* __restrict__ value,
                                                 const float* __restrict__ mask) {
    int c  = blockIdx.x;
    int bn = blockIdx.z * N_ + blockIdx.y;
    int t  = threadIdx.x;
    const float4* v4 = (const float4*)(value + ((size_t)bn * C_ + c) * HW_);
    const float4* m4 = (const float4*)(mask + (size_t)bn * HW_);
    float ws = 0.f, vs = 0.f, ms = 0.f;
    #pragma unroll
    for (int i = 0; i < 9; i++) {                          // 9216/4/256 = 9
        float4 v = v4[i * 256 + t];
        float4 m = m4[i * 256 + t];
        ws += v.x * m.x + v.y * m.y + v.z * m.z + v.w * m.w;
        vs += v.x + v.y + v.z + v.w;
        ms += m.x + m.y + m.z + m.w;
    }
    ws = warpSum(ws); vs = warpSum(vs);
    __shared__ float sw[8], sv[8], sm[8];
    if ((t & 31) == 0) { sw[t >> 5] = ws; sv[t >> 5] = vs; }
    if (c == 0) {
        ms = warpSum(ms);
        if ((t & 31) == 0) sm[t >> 5] = ms;
    }
    __syncthreads();
    if (t == 0) {
        float a = 0.f, b = 0.f;
        #pragma unroll
        for (int i = 0; i < 8; i++) { a += sw[i]; b += sv[i]; }
        d_wsum[bn * C_ + c] = a;
        d_vsum[bn * C_ + c] = b;
        if (c == 0) {
            float r = 0.f;
            #pragma unroll
            for (int i = 0; i < 8; i++) r += sm[i];
            d_msum[bn] = r;
        }
    }
}

// ---------------- kernel 2: policy + bank update ----------------------------
// grid 16, 256 threads. Warp w owns slot w.
__global__ void __launch_bounds__(256) k_policy(const float* __restrict__ proto,
                                                const float* __restrict__ age,
                                                const float* __restrict__ usage,
                                                const float* __restrict__ conf,
                                                const void* __restrict__ valid) {
    int bn = blockIdx.x, t = threadIdx.x;
    int w = t >> 5, l = t & 31;
    __shared__ float s_cand[C_], s_sim[K_], s_red[8], s_redU[8];
    __shared__ float s_vldf[K_], s_am, s_um;
    __shared__ int s_mode;
    __shared__ int s_upd, s_act;

    // valid dtype sniff + global age/usage maxes
    if (t == 0) {
        const unsigned int* wd = (const unsigned int*)valid;
        int isInt = 1, isFlt = 1;
        for (int i = 0; i < 32; i++) {
            unsigned int x = wd[i];
            isInt &= (x <= 1u);
            isFlt &= (x == 0u || x == 0x3f800000u);
        }
        s_mode = isInt ? 1 : (isFlt ? 2 : 0);
    }
    {
        float a = (t < 128) ? age[t]   : -1e30f;
        float u = (t < 128) ? usage[t] : -1e30f;
        a = warpMax(a); u = warpMax(u);
        if (l == 0) { s_red[w] = a; s_redU[w] = u; }
    }
    __syncthreads();
    if (t == 0) {
        float A = -1e30f, U = -1e30f;
        #pragma unroll
        for (int i = 0; i < 8; i++) { A = fmaxf(A, s_red[i]); U = fmaxf(U, s_redU[i]); }
        s_am = fmaxf(A, 1.0f); s_um = fmaxf(U, 1.0f);
    }
    __syncthreads();              // s_mode visible before decode
    if (t < K_) {
        int idx = bn * K_ + t, v;
        if (s_mode == 1)      v = ((const int*)valid)[idx] != 0;
        else if (s_mode == 2) v = ((const float*)valid)[idx] != 0.0f;
        else                  v = ((const unsigned char*)valid)[idx] != 0;
        s_vldf[t] = v ? 1.0f : 0.0f;
    }
    __syncthreads();

    // candidate prototype (channel t), l2-normalized
    float msum = d_msum[bn];
    float cc = (msum <= 1e-5f)
             ? d_vsum[bn * C_ + t] * (1.0f / (float)HW_)
             : d_wsum[bn * C_ + t] / fmaxf(msum, 1e-6f);
    float ss = warpSum(cc * cc);
    if (l == 0) s_red[w] = ss;
    __syncthreads();
    float tot = 0.f;
    #pragma unroll
    for (int i = 0; i < 8; i++) tot += s_red[i];
    float cn = cc / fmaxf(sqrtf(tot), 1e-12f);
    s_cand[t] = cn;
    __syncthreads();

    // sim[k]: warp w handles slot w
    const float* pbase = proto + (size_t)bn * K_ * C_;
    {
        float ps = 0.f, pd = 0.f;
        #pragma unroll
        for (int i = 0; i < 8; i++) {
            float p = pbase[w * C_ + i * 32 + l];
            ps += p * p;
            pd += p * s_cand[i * 32 + l];
        }
        ps = warpSum(ps); pd = warpSum(pd);
        if (l == 0) {
            float sim = pd / fmaxf(sqrtf(ps), 1e-12f);
            s_sim[w] = (s_vldf[w] > 0.5f) ? sim : -1.0f;
        }
    }
    __syncthreads();

    // decision (thread 0)
    if (t == 0) {
        bool v[K_]; bool anyv = false, anyi = false;
        #pragma unroll
        for (int k = 0; k < K_; k++) {
            v[k] = (s_vldf[k] > 0.5f);
            anyv |= v[k]; anyi |= !v[k];
        }
        float best = -1e30f; int tgt = 0;
        #pragma unroll
        for (int k = 0; k < K_; k++) if (s_sim[k] > best) { best = s_sim[k]; tgt = k; }
        int target = anyv ? tgt : 0;
        float msim = anyv ? s_sim[target] : -1.0f;
        int action = (!anyv) ? 3 : ((msim >= 0.8f) ? 1 : ((msim >= 0.3f) ? 0 : 3));
        float bs = -1e30f; int vic = 0;
        #pragma unroll
        for (int k = 0; k < K_; k++) {
            float sc = age[bn * K_ + k] / s_am
                     + (1.0f - usage[bn * K_ + k] / s_um)
                     + (1.0f - conf[bn * K_ + k]);
            if (sc > bs) { bs = sc; vic = k; }
        }
        int fe = 0;
        for (int k = 0; k < K_; k++) { if (!v[k]) { fe = k; break; } }
        int spawn = anyi ? fe : vic;
        s_upd = (action == 1) ? target : spawn;
        s_act = (action == 1) ? 1 : ((action == 3) ? 2 : 0);  // 1=refine, 2=spawn
        d_anyv[bn] = (anyv || action == 3) ? 1 : 0;
    }
    __syncthreads();
    int upd = s_upd, mode = s_act;

    // per-warp slot update: warp w owns slot w
    {
        float pn[8]; float q = 0.f;
        #pragma unroll
        for (int i = 0; i < 8; i++) {
            float p = pbase[w * C_ + i * 32 + l];
            float x = p;
            if (w == upd) {
                if (mode == 1)      x = 0.7f * p + 0.3f * s_cand[i * 32 + l];
                else if (mode == 2) x = s_cand[i * 32 + l];
            }
            pn[i] = x; q += x * x;
        }
        q = warpSum(q);
        float inv = 1.0f / fmaxf(sqrtf(q), 1e-12f);
        size_t o = (size_t)bn * K_ * C_ + (size_t)w * C_;
        bool storeNorm = (w == upd && mode == 1);
        #pragma unroll
        for (int i = 0; i < 8; i++) {
            float pw = storeNorm ? pn[i] * inv : pn[i];
            d_pnew[o + i * 32 + l] = pw;
            d_bnn [o + i * 32 + l] = pn[i] * inv;
        }
        if (l == 0) {
            bool vk = (s_vldf[w] > 0.5f);
            d_vldn[bn * K_ + w] = (vk || (mode == 2 && w == upd)) ? 1.0f : 0.0f;
        }
    }
}

// ---------------- kernel 3: fused readout, smem-staged tile -----------------
// grid (HW/64, N, B) = 2304 blocks, 256 threads, 96KB dynamic smem.
// Value read ONCE from DRAM per pixel (staged), both scans run from smem.
// smem layout (floats):
//   tile [C][PX]            0      .. 16384
//   bnnT [C][8]             16384  .. 18432
//   pnT  [C][8]             18432  .. 20480
//   part [4][PX][12]        20480  .. 23552
//   attn [PX][8]            23552  .. 24064
//   vld  [8]                24064  .. 24072
#define SM_TILE 0
#define SM_BNN  16384
#define SM_PN   18432
#define SM_PART 20480
#define SM_ATTN 23552
#define SM_VLD  24064
#define SM_FLOATS 24072

__global__ void __launch_bounds__(256) k_readout(const float* __restrict__ value,
                                                 const float* __restrict__ frame,
                                                 const float* __restrict__ pgate,
                                                 const float* __restrict__ fgate,
                                                 float* __restrict__ out) {
    extern __shared__ float smf[];
    __shared__ int s_any;
    int tile = blockIdx.x, n = blockIdx.y, b = blockIdx.z;
    int bn = b * N_ + n;
    int t = threadIdx.x;
    int px = t & 63, q = t >> 6;         // pixel lane, channel quarter
    int pix0 = tile * PX_;

    // ---- load prototypes (transposed) + flags ------------------------------
    const size_t off = (size_t)bn * K_ * C_;
    #pragma unroll
    for (int i = 0; i < 8; i++) {
        int j = i * 256 + t;             // j = k*C + c
        int k = j >> 8, c = j & 255;
        smf[SM_BNN + c * 8 + k] = d_bnn[off + j];
        smf[SM_PN  + c * 8 + k] = d_pnew[off + j];
    }
    if (t < K_) smf[SM_VLD + t] = d_vldn[bn * K_ + t];
    if (t == 0) s_any = d_anyv[bn];

    // ---- stage value tile: 256 rows x 64 px, coalesced float4 rows ---------
    const float* vbase = value + (size_t)bn * C_ * HW_ + pix0;
    #pragma unroll
    for (int i = 0; i < 16; i++) {
        int j = i * 256 + t;             // 4096 float4 chunks
        int row = j >> 4, col = j & 15;  // 16 float4 per row
        float4 v = *(const float4*)(vbase + (size_t)row * HW_ + col * 4);
        *(float4*)&smf[SM_TILE + row * PX_ + col * 4] = v;
    }
    __syncthreads();

    // ---- scan 1: partial rsim + ||v||^2 over this thread's 64 channels -----
    {
        float r[K_]; float ns = 0.f;
        #pragma unroll
        for (int k = 0; k < K_; k++) r[k] = 0.f;
        int cbase = q * 64;
        #pragma unroll 8
        for (int ci = 0; ci < 64; ci++) {
            int c = cbase + ci;
            float v = smf[SM_TILE + c * PX_ + px];
            ns += v * v;
            float4 b0 = *(const float4*)&smf[SM_BNN + c * 8];
            float4 b1 = *(const float4*)&smf[SM_BNN + c * 8 + 4];
            r[0] += b0.x * v; r[1] += b0.y * v; r[2] += b0.z * v; r[3] += b0.w * v;
            r[4] += b1.x * v; r[5] += b1.y * v; r[6] += b1.z * v; r[7] += b1.w * v;
        }
        float* pp = &smf[SM_PART + (q * PX_ + px) * 12];
        pp[0] = ns;
        #pragma unroll
        for (int k = 0; k < K_; k++) pp[1 + k] = r[k];
    }
    __syncthreads();

    // ---- per-pixel softmax (threads 0..63) ---------------------------------
    if (t < PX_) {
        float ns = 0.f, r[K_];
        #pragma unroll
        for (int k = 0; k < K_; k++) r[k] = 0.f;
        #pragma unroll
        for (int qq = 0; qq < 4; qq++) {
            const float* pp = &smf[SM_PART + (qq * PX_ + t) * 12];
            ns += pp[0];
            #pragma unroll
            for (int k = 0; k < K_; k++) r[k] += pp[1 + k];
        }
        float inv = 1.0f / fmaxf(sqrtf(ns), 1e-12f);
        float a[K_];
        if (!s_any) {
            #pragma unroll
            for (int k = 0; k < K_; k++) a[k] = 0.f;
        } else {
            float m = -1e30f;
            #pragma unroll
            for (int k = 0; k < K_; k++)
                if (smf[SM_VLD + k] > 0.5f) m = fmaxf(m, r[k] * inv);
            float tot = 0.f;
            #pragma unroll
            for (int k = 0; k < K_; k++) {
                float e = (smf[SM_VLD + k] > 0.5f) ? __expf(r[k] * inv - m) : 0.f;
                a[k] = e; tot += e;
            }
            float z = 1.0f / tot;
            #pragma unroll
            for (int k = 0; k < K_; k++) a[k] *= z;
        }
        #pragma unroll
        for (int k = 0; k < K_; k++) smf[SM_ATTN + t * 8 + k] = a[k];
    }
    __syncthreads();

    // ---- scan 2: blend + store (value from smem, frame GMEM/L2) ------------
    {
        float4 A0 = *(const float4*)&smf[SM_ATTN + px * 8];
        float4 A1 = *(const float4*)&smf[SM_ATTN + px * 8 + 4];
        float pg = *pgate, fg = *fgate;
        const float* fbase = frame + (size_t)b * C_ * HW_ + pix0 + px;
        float* obase = out + (size_t)bn * C_ * HW_ + pix0 + px;
        int cbase = q * 64;
        #pragma unroll 8
        for (int ci = 0; ci < 64; ci++) {
            int c = cbase + ci;
            float v = smf[SM_TILE + c * PX_ + px];
            float f = fbase[(size_t)c * HW_];
            float4 p0 = *(const float4*)&smf[SM_PN + c * 8];
            float4 p1 = *(const float4*)&smf[SM_PN + c * 8 + 4];
            float pm = A0.x * p0.x + A0.y * p0.y + A0.z * p0.z + A0.w * p0.w
                     + A1.x * p1.x + A1.y * p1.y + A1.z * p1.z + A1.w * p1.w;
            obase[(size_t)c * HW_] = v + pg * pm + fg * f;
        }
    }
}

// ---------------- launch ----------------------------------------------------
extern "C" void kernel_launch(void* const* d_in, const int* in_sizes, int n_in,
                              void* d_out, int out_size) {
    const float* value = (const float*)d_in[0];
    const float* frame = (const float*)d_in[1];
    const float* mask  = (const float*)d_in[2];
    const float* proto = (const float*)d_in[3];
    const float* age   = (const float*)d_in[4];
    const float* usage = (const float*)d_in[5];
    const float* conf  = (const float*)d_in[6];
    // d_in[7..10] = W1, b1, W2, b2: dead code (logits unused by the output)
    const float* pgate = (const float*)d_in[11];
    const float* fgate = (const float*)d_in[12];
    const void*  valid = (const void*)d_in[13];
    float* out = (float*)d_out;

    const int smemBytes = SM_FLOATS * sizeof(float);   // ~96 KB
    cudaFuncSetAttribute(k_readout, cudaFuncAttributeMaxDynamicSharedMemorySize,
                         smemBytes);

    dim3 gc(C_, N_, B_);
    k_candsum<<<gc, 256>>>(value, mask);
    k_policy<<<BN_, 256>>>(proto, age, usage, conf, valid);
    dim3 gr(HW_ / PX_, N_, B_);
    k_readout<<<gr, 256, smemBytes>>>(value, frame, pgate, fgate, out);
}